// round 8
// baseline (speedup 1.0000x reference)
#include <cuda_runtime.h>
#include <cuda_fp16.h>
#include <math.h>

typedef unsigned int u32;
typedef unsigned long long u64;

// Problem constants
constexpr int B_    = 8192;
constexpr int NE_   = 20000;
constexpr int H_    = 512;
constexpr int C_    = 50;
constexpr int KIN_  = 25600;          // C_*H_

// ---------------- scratch (static device memory; no allocations) -------------
__device__ float g_xs[(size_t)B_ * 3 * H_];
__device__ float g_part0[B_ * 6];
__device__ float g_s0[3], g_t0[3];
__device__ float g_part1[B_ * 100];
__device__ float g_s1[C_], g_t1[C_];
__device__ __half g_a16[(size_t)B_ * KIN_];    // A fp16 (420 MB)
__device__ __half g_w16[(size_t)H_ * KIN_];    // fc_w fp16
__device__ __half g_e16[(size_t)NE_ * H_];     // ent fp16
__device__ __half g_z16[(size_t)B_ * H_];      // z fp16
__device__ float g_fc[B_ * H_];
__device__ float g_part2[256 * 1024];
__device__ float g_s2[H_], g_t2[H_];

// ---------------- PTX helpers (portable: sm_80+ instructions only) -----------
static __device__ __forceinline__ u32 smem_u32(const void* p) {
    u32 a;
    asm("{ .reg .u64 t; cvta.to.shared.u64 t, %1; cvt.u32.u64 %0, t; }" : "=r"(a) : "l"(p));
    return a;
}

#define CP_ASYNC16(saddr, gptr, srcsz) \
    asm volatile("cp.async.cg.shared.global [%0], [%1], 16, %2;" \
                 :: "r"(saddr), "l"(gptr), "r"(srcsz) : "memory")
#define CP_COMMIT() asm volatile("cp.async.commit_group;" ::: "memory")

#define LDM_X4(r0, r1, r2, r3, addr) \
    asm volatile("ldmatrix.sync.aligned.m8n8.x4.shared.b16 {%0,%1,%2,%3}, [%4];" \
                 : "=r"(r0), "=r"(r1), "=r"(r2), "=r"(r3) : "r"(addr))

#define MMA16816(d, a, b0, b1) \
    asm volatile("mma.sync.aligned.m16n8k16.row.col.f32.f16.f16.f32 " \
                 "{%0,%1,%2,%3},{%4,%5,%6,%7},{%8,%9},{%0,%1,%2,%3};" \
                 : "+f"((d)[0]), "+f"((d)[1]), "+f"((d)[2]), "+f"((d)[3]) \
                 : "r"((a)[0]), "r"((a)[1]), "r"((a)[2]), "r"((a)[3]), \
                   "r"(b0), "r"(b1))

// ======================= K1: gather + bn0 partial stats ======================
__global__ void k_gather(const int* __restrict__ facts, const float* __restrict__ ent,
                         const float* __restrict__ rel, const float* __restrict__ erb)
{
    int b = blockIdx.x, t = threadIdx.x;
    int f0 = facts[b * 3 + 0];
    int f1 = facts[b * 3 + 1];
    const float* r0 = ent + (size_t)f0 * H_;
    const float* r1 = rel + (size_t)f1 * H_;
    const float* r2 = erb + (size_t)f0 * H_;
    float* xb = g_xs + (size_t)b * 3 * H_;

    float s[3] = {0.f, 0.f, 0.f}, q[3] = {0.f, 0.f, 0.f};
    for (int h = t; h < H_; h += 128) {
        float v0 = r0[h], v1 = r1[h], v2 = r2[h];
        xb[h] = v0; xb[H_ + h] = v1; xb[2 * H_ + h] = v2;
        s[0] += v0; q[0] += v0 * v0;
        s[1] += v1; q[1] += v1 * v1;
        s[2] += v2; q[2] += v2 * v2;
    }
    __shared__ float red[4][6];
    #pragma unroll
    for (int i = 0; i < 3; i++) {
        #pragma unroll
        for (int o = 16; o; o >>= 1) {
            s[i] += __shfl_xor_sync(0xffffffffu, s[i], o);
            q[i] += __shfl_xor_sync(0xffffffffu, q[i], o);
        }
    }
    int w = t >> 5, ln = t & 31;
    if (ln == 0) {
        #pragma unroll
        for (int i = 0; i < 3; i++) { red[w][i] = s[i]; red[w][3 + i] = q[i]; }
    }
    __syncthreads();
    if (t < 6) g_part0[b * 6 + t] = red[0][t] + red[1][t] + red[2][t] + red[3][t];
}

// ======================= K2: finalize bn0 =====================================
__global__ void k_fin0(const float* __restrict__ gg, const float* __restrict__ bb)
{
    __shared__ double sd[256];
    __shared__ double tot[6];
    int t = threadIdx.x;
    for (int st = 0; st < 6; st++) {
        double a = 0.0;
        for (int j = t; j < B_; j += 256) a += (double)g_part0[j * 6 + st];
        sd[t] = a; __syncthreads();
        for (int o = 128; o; o >>= 1) { if (t < o) sd[t] += sd[t + o]; __syncthreads(); }
        if (t == 0) tot[st] = sd[0];
        __syncthreads();
    }
    if (t < 3) {
        double cnt  = (double)B_ * (double)H_;
        double mean = tot[t] / cnt;
        double var  = tot[3 + t] / cnt - mean * mean;
        double sc   = (double)gg[t] / sqrt(var + 1e-5);
        g_s0[t] = (float)sc;
        g_t0[t] = (float)((double)bb[t] - mean * sc);
    }
}

// ======================= K3: conv + bn1 partial stats =========================
__global__ void k_conv_stats(const float* __restrict__ cw, const float* __restrict__ cb)
{
    __shared__ float xn[3][514];
    __shared__ float w[450];
    __shared__ float cbs[C_];
    __shared__ float ssum[C_], ssq[C_];
    int b = blockIdx.x, t = threadIdx.x;

    for (int i = t; i < 450; i += 256) w[i] = cw[i];
    if (t < C_) { cbs[t] = cb[t]; ssum[t] = 0.f; ssq[t] = 0.f; }
    for (int i = t; i < 3 * H_; i += 256) {
        int ch = i >> 9, h = i & 511;
        xn[ch][h + 1] = g_xs[((size_t)b * 3 + ch) * H_ + h] * g_s0[ch] + g_t0[ch];
    }
    if (t < 3) { xn[t][0] = 0.f; xn[t][513] = 0.f; }
    __syncthreads();

    for (int c = 0; c < C_; c++) {
        float w0 = w[c*9+0], w1 = w[c*9+1], w2 = w[c*9+2];
        float w3 = w[c*9+3], w4 = w[c*9+4], w5 = w[c*9+5];
        float w6 = w[c*9+6], w7 = w[c*9+7], w8 = w[c*9+8];
        float bs = 0.f, bq = 0.f;
        #pragma unroll
        for (int hh = 0; hh < 2; hh++) {
            int h = t + hh * 256;
            float y = cbs[c]
                + w0 * xn[0][h] + w1 * xn[0][h + 1] + w2 * xn[0][h + 2]
                + w3 * xn[1][h] + w4 * xn[1][h + 1] + w5 * xn[1][h + 2]
                + w6 * xn[2][h] + w7 * xn[2][h + 1] + w8 * xn[2][h + 2];
            bs += y; bq += y * y;
        }
        #pragma unroll
        for (int o = 16; o; o >>= 1) {
            bs += __shfl_xor_sync(0xffffffffu, bs, o);
            bq += __shfl_xor_sync(0xffffffffu, bq, o);
        }
        if ((t & 31) == 0) { atomicAdd(&ssum[c], bs); atomicAdd(&ssq[c], bq); }
    }
    __syncthreads();
    if (t < C_) {
        g_part1[(size_t)b * 100 + t]      = ssum[t];
        g_part1[(size_t)b * 100 + 50 + t] = ssq[t];
    }
}

// ======================= K4: finalize bn1 =====================================
__global__ void k_fin1(const float* __restrict__ gg, const float* __restrict__ bb)
{
    int c = blockIdx.x, t = threadIdx.x;
    __shared__ double sd[256];
    __shared__ double tS;
    double s = 0.0, q = 0.0;
    for (int j = t; j < B_; j += 256) {
        s += (double)g_part1[(size_t)j * 100 + c];
        q += (double)g_part1[(size_t)j * 100 + 50 + c];
    }
    sd[t] = s; __syncthreads();
    for (int o = 128; o; o >>= 1) { if (t < o) sd[t] += sd[t + o]; __syncthreads(); }
    if (t == 0) tS = sd[0];
    __syncthreads();
    sd[t] = q; __syncthreads();
    for (int o = 128; o; o >>= 1) { if (t < o) sd[t] += sd[t + o]; __syncthreads(); }
    if (t == 0) {
        double cnt  = (double)B_ * (double)H_;
        double mean = tS / cnt;
        double var  = sd[0] / cnt - mean * mean;
        double sc   = (double)gg[c] / sqrt(var + 1e-5);
        g_s1[c] = (float)sc;
        g_t1[c] = (float)((double)bb[c] - mean * sc);
    }
}

// ======================= K5: build A (fp16) ===================================
__global__ void k_build(const float* __restrict__ cw, const float* __restrict__ cb)
{
    __shared__ float xn[3][514];
    __shared__ float w[450];
    __shared__ float cbs[C_];
    __shared__ float s1s[C_], t1s[C_];
    int b = blockIdx.x, t = threadIdx.x;

    for (int i = t; i < 450; i += 256) w[i] = cw[i];
    if (t < C_) { cbs[t] = cb[t]; s1s[t] = g_s1[t]; t1s[t] = g_t1[t]; }
    for (int i = t; i < 3 * H_; i += 256) {
        int ch = i >> 9, h = i & 511;
        xn[ch][h + 1] = g_xs[((size_t)b * 3 + ch) * H_ + h] * g_s0[ch] + g_t0[ch];
    }
    if (t < 3) { xn[t][0] = 0.f; xn[t][513] = 0.f; }
    __syncthreads();

    __half* arow = g_a16 + (size_t)b * KIN_;
    for (int c = 0; c < C_; c++) {
        float w0 = w[c*9+0], w1 = w[c*9+1], w2 = w[c*9+2];
        float w3 = w[c*9+3], w4 = w[c*9+4], w5 = w[c*9+5];
        float w6 = w[c*9+6], w7 = w[c*9+7], w8 = w[c*9+8];
        float sc = s1s[c], tc = t1s[c], cbc = cbs[c];
        #pragma unroll
        for (int hh = 0; hh < 2; hh++) {
            int h = t + hh * 256;
            float y = cbc
                + w0 * xn[0][h] + w1 * xn[0][h + 1] + w2 * xn[0][h + 2]
                + w3 * xn[1][h] + w4 * xn[1][h + 1] + w5 * xn[1][h + 2]
                + w6 * xn[2][h] + w7 * xn[2][h + 1] + w8 * xn[2][h + 2];
            float r = fmaxf(fmaf(y, sc, tc), 0.f);
            arow[c * H_ + h] = __float2half_rn(r);
        }
    }
}

// ======================= split: fp32 -> fp16 ==================================
__global__ void k_cvt16(const float* __restrict__ src, __half* __restrict__ dst, long long n)
{
    long long i = (long long)blockIdx.x * 256 + threadIdx.x;
    if (i < n) dst[i] = __float2half_rn(src[i]);
}

// ======================= fp16 NT GEMM v2 (mma.sync m16n8k16) ==================
// C[m,n] = sum_k A[m,k] * B[n,k].  A: MxK row-major fp16, B: NxK row-major fp16.
// CTA tile 128x128, 4 warps (2m x 2n), warp tile 64x64. K-tile 64.
// 3-stage cp.async pipeline + register double-buffered fragments. Occupancy 2.
// Requires M%128==0, K%64==0; N%8==0 (guarded).
constexpr int RB   = 144;                    // padded row bytes (64 fp16 + 8 pad)
constexpr int ASZ  = 128 * RB;               // 18432 B (A or B tile)
constexpr int STG  = 2 * ASZ;                // 36864 B per stage (A + B)
constexpr int NSTG = 3;
constexpr int GEMM_SMEM = NSTG * STG;        // 110592 B

__global__ __launch_bounds__(128, 2)
void k_gemm(const __half* __restrict__ A, const __half* __restrict__ Bm,
            float* __restrict__ Cm, int N, int Kd, const float* __restrict__ bias)
{
    extern __shared__ char smem[];
    const u32 sb = smem_u32(smem);
    const int tid  = threadIdx.x;
    const int w    = tid >> 5, lane = tid & 31;
    const int mBase = blockIdx.x * 128;
    const int nBase = blockIdx.y * 128;

    // cp.async geometry: thread covers rows r0+16i (i=0..7), fixed col chunk
    const int r0  = tid >> 3;                 // 0..15
    const int c8  = (tid & 7) * 8;            // element column offset
    const u32 sA0 = (u32)r0 * RB + (u32)(tid & 7) * 16;
    const __half* Agp = A + (size_t)(mBase + r0) * Kd + c8;
    const int nr0 = nBase + r0;
    const size_t rowStep = (size_t)16 * Kd;

    const int nT = Kd >> 6;

    // warp layout: wm in {0,64}, wn in {0,64}
    const int wm = (w & 1) * 64;
    const int wn = (w >> 1) * 64;
    const u32 lrow = (lane & 15), lhalf = (lane >> 4) << 4;
    u32 aRel[4], bRel[4];
    #pragma unroll
    for (int i = 0; i < 4; i++) aRel[i] = (wm + i * 16 + lrow) * RB + lhalf;
    #pragma unroll
    for (int j = 0; j < 4; j++) bRel[j] = ASZ + (wn + j * 16 + lrow) * RB + lhalf;

    float acc[4][8][4];
    #pragma unroll
    for (int i = 0; i < 4; i++)
        #pragma unroll
        for (int j = 0; j < 8; j++)
            #pragma unroll
            for (int q = 0; q < 4; q++) acc[i][j][q] = 0.f;

    // prologue: stages 0..NSTG-2
    #pragma unroll
    for (int p = 0; p < NSTG - 1; p++) {
        if (p < nT) {
            const u32 st = sb + p * STG;
            const size_t ko = (size_t)p * 64;
            #pragma unroll
            for (int i = 0; i < 8; i++)
                CP_ASYNC16(st + sA0 + i * (16 * RB), Agp + i * rowStep + ko, 16u);
            #pragma unroll
            for (int i = 0; i < 8; i++) {
                int n = nr0 + i * 16;
                int ok = (n < N);
                const __half* gp = Bm + (size_t)(ok ? n : 0) * Kd + c8 + ko;
                CP_ASYNC16(st + ASZ + sA0 + i * (16 * RB), gp, ok ? 16u : 0u);
            }
        }
        CP_COMMIT();
    }

    for (int t = 0; t < nT; t++) {
        asm volatile("cp.async.wait_group 1;" ::: "memory");
        __syncthreads();

        // issue K-tile t+NSTG-1 into its stage (empty commit keeps ledger uniform)
        {
            int nt = t + NSTG - 1;
            if (nt < nT) {
                const u32 st = sb + (nt % NSTG) * STG;
                const size_t ko = (size_t)nt * 64;
                #pragma unroll
                for (int i = 0; i < 8; i++)
                    CP_ASYNC16(st + sA0 + i * (16 * RB), Agp + i * rowStep + ko, 16u);
                #pragma unroll
                for (int i = 0; i < 8; i++) {
                    int n = nr0 + i * 16;
                    int ok = (n < N);
                    const __half* gp = Bm + (size_t)(ok ? n : 0) * Kd + c8 + ko;
                    CP_ASYNC16(st + ASZ + sA0 + i * (16 * RB), gp, ok ? 16u : 0u);
                }
            }
            CP_COMMIT();
        }

        const u32 stoff = sb + (t % NSTG) * STG;
        u32 ar[2][4][4], br[2][4][4];
        // prefetch s=0 fragments
        #pragma unroll
        for (int i = 0; i < 4; i++)
            LDM_X4(ar[0][i][0], ar[0][i][1], ar[0][i][2], ar[0][i][3], stoff + aRel[i]);
        #pragma unroll
        for (int j = 0; j < 4; j++)
            LDM_X4(br[0][j][0], br[0][j][1], br[0][j][2], br[0][j][3], stoff + bRel[j]);

        #pragma unroll
        for (int s = 0; s < 4; s++) {
            const int cur = s & 1;
            if (s < 3) {
                const int nxt = cur ^ 1;
                #pragma unroll
                for (int i = 0; i < 4; i++)
                    LDM_X4(ar[nxt][i][0], ar[nxt][i][1], ar[nxt][i][2], ar[nxt][i][3],
                           stoff + aRel[i] + (s + 1) * 32);
                #pragma unroll
                for (int j = 0; j < 4; j++)
                    LDM_X4(br[nxt][j][0], br[nxt][j][1], br[nxt][j][2], br[nxt][j][3],
                           stoff + bRel[j] + (s + 1) * 32);
            }
            #pragma unroll
            for (int i = 0; i < 4; i++) {
                #pragma unroll
                for (int j = 0; j < 8; j++) {
                    MMA16816(acc[i][j], ar[cur][i],
                             br[cur][j >> 1][j & 1], br[cur][j >> 1][(j & 1) + 2]);
                }
            }
        }
    }

    // epilogue
    const int mRow = mBase + wm + (lane >> 2);
    const int nCol = nBase + wn + ((lane & 3) << 1);
    #pragma unroll
    for (int i = 0; i < 4; i++) {
        #pragma unroll
        for (int j = 0; j < 8; j++) {
            int n = nCol + j * 8;
            if (n < N) {
                float bx = 0.f, by = 0.f;
                if (bias) { bx = bias[n]; by = bias[n + 1]; }
                int m0 = mRow + i * 16;
                float2 v0; v0.x = acc[i][j][0] + bx; v0.y = acc[i][j][1] + by;
                float2 v1; v1.x = acc[i][j][2] + bx; v1.y = acc[i][j][3] + by;
                *(float2*)(Cm + (size_t)m0 * N + n) = v0;
                *(float2*)(Cm + (size_t)(m0 + 8) * N + n) = v1;
            }
        }
    }
}

// ======================= K7: bn2 partial stats ================================
__global__ void k_stats2_part()
{
    int blk = blockIdx.x, t = threadIdx.x;
    float s0 = 0.f, q0 = 0.f, s1 = 0.f, q1 = 0.f;
    int r0 = blk * 32;
    for (int r = 0; r < 32; r++) {
        const float* row = g_fc + (size_t)(r0 + r) * H_;
        float a = row[t];
        float b = row[t + 256];
        s0 += a; q0 += a * a;
        s1 += b; q1 += b * b;
    }
    g_part2[blk * 1024 + t]       = s0;
    g_part2[blk * 1024 + 256 + t] = q0;
    g_part2[blk * 1024 + 512 + t] = s1;
    g_part2[blk * 1024 + 768 + t] = q1;
}

// ======================= K8: finalize bn2 =====================================
__global__ void k_fin2(const float* __restrict__ gg, const float* __restrict__ bb)
{
    int n = blockIdx.x * 256 + threadIdx.x;
    int so = (n < 256) ? n : (256 + n);
    int qo = so + 256;
    double s = 0.0, q = 0.0;
    for (int j = 0; j < 256; j++) {
        s += (double)g_part2[j * 1024 + so];
        q += (double)g_part2[j * 1024 + qo];
    }
    double mean = s / (double)B_;
    double var  = q / (double)B_ - mean * mean;
    double sc   = (double)gg[n] / sqrt(var + 1e-5);
    g_s2[n] = (float)sc;
    g_t2[n] = (float)((double)bb[n] - mean * sc);
}

// ======================= K9: bn2+relu -> z fp16 ===============================
__global__ void k_bn2relu()
{
    int idx = blockIdx.x * 256 + threadIdx.x;     // over B_*H_
    int c = idx & 511;
    float v = fmaxf(fmaf(g_fc[idx], g_s2[c], g_t2[c]), 0.f);
    g_z16[idx] = __float2half_rn(v);
}

// ======================= K11: row log_softmax (online, 2 passes) ==============
__global__ void k_lsm(float* __restrict__ out)
{
    int b = blockIdx.x, t = threadIdx.x;
    float* p = out + (size_t)b * NE_;
    __shared__ float rm[8], rs[8];
    __shared__ float lseS;

    float m = -3.0e38f, s = 0.f;
    for (int i = t; i < NE_; i += 256) {
        float v = p[i];
        if (v > m) { s = s * __expf(m - v) + 1.f; m = v; }
        else       { s += __expf(v - m); }
    }
    #pragma unroll
    for (int o = 16; o; o >>= 1) {
        float mo = __shfl_xor_sync(0xffffffffu, m, o);
        float so = __shfl_xor_sync(0xffffffffu, s, o);
        float M = fmaxf(m, mo);
        s = s * __expf(m - M) + so * __expf(mo - M);
        m = M;
    }
    if ((t & 31) == 0) { rm[t >> 5] = m; rs[t >> 5] = s; }
    __syncthreads();
    if (t == 0) {
        float M = rm[0], S = rs[0];
        for (int j = 1; j < 8; j++) {
            float M2 = fmaxf(M, rm[j]);
            S = S * __expf(M - M2) + rs[j] * __expf(rm[j] - M2);
            M = M2;
        }
        lseS = M + logf(S);
    }
    __syncthreads();
    float lse = lseS;
    for (int i = t; i < NE_; i += 256) p[i] -= lse;
}

// ======================= launch ===============================================
extern "C" void kernel_launch(void* const* d_in, const int* in_sizes, int n_in,
                              void* d_out, int out_size)
{
    const int*   facts = (const int*)  d_in[0];
    const float* ent   = (const float*)d_in[1];
    const float* rel   = (const float*)d_in[2];
    const float* erb   = (const float*)d_in[3];
    const float* cw    = (const float*)d_in[4];
    const float* cb    = (const float*)d_in[5];
    const float* fcw   = (const float*)d_in[6];
    const float* fcb   = (const float*)d_in[7];
    const float* b0g   = (const float*)d_in[8];
    const float* b0b   = (const float*)d_in[9];
    const float* b1g   = (const float*)d_in[10];
    const float* b1b   = (const float*)d_in[11];
    const float* b2g   = (const float*)d_in[12];
    const float* b2b   = (const float*)d_in[13];
    float* out = (float*)d_out;

    cudaFuncSetAttribute(k_gemm, cudaFuncAttributeMaxDynamicSharedMemorySize, GEMM_SMEM);

    __half *p_a16, *p_w16, *p_e16, *p_z16;
    float *p_fc;
    cudaGetSymbolAddress((void**)&p_a16, g_a16);
    cudaGetSymbolAddress((void**)&p_w16, g_w16);
    cudaGetSymbolAddress((void**)&p_e16, g_e16);
    cudaGetSymbolAddress((void**)&p_z16, g_z16);
    cudaGetSymbolAddress((void**)&p_fc,  g_fc);

    k_gather<<<B_, 128>>>(facts, ent, rel, erb);
    k_fin0<<<1, 256>>>(b0g, b0b);
    k_conv_stats<<<B_, 256>>>(cw, cb);
    k_fin1<<<C_, 256>>>(b1g, b1b);
    k_build<<<B_, 256>>>(cw, cb);

    {
        long long nW = (long long)H_ * KIN_;
        k_cvt16<<<(u32)((nW + 255) / 256), 256>>>(fcw, p_w16, nW);
        long long nE = (long long)NE_ * H_;
        k_cvt16<<<(u32)((nE + 255) / 256), 256>>>(ent, p_e16, nE);
    }

    // FC: (8192, 25600) x (512, 25600)^T -> (8192, 512), + bias
    k_gemm<<<dim3(B_ / 128, H_ / 128), 128, GEMM_SMEM>>>(
        p_a16, p_w16, p_fc, H_, KIN_, fcb);

    k_stats2_part<<<256, 256>>>();
    k_fin2<<<2, 256>>>(b2g, b2b);
    k_bn2relu<<<(B_ * H_) / 256, 256>>>();

    // score: (8192, 512) x (20000, 512)^T -> (8192, 20000)
    k_gemm<<<dim3(B_ / 128, (NE_ + 127) / 128), 128, GEMM_SMEM>>>(
        p_z16, p_e16, out, NE_, H_, nullptr);

    k_lsm<<<B_, 256>>>(out);
}

// round 9
// speedup vs baseline: 1.5369x; 1.5369x over previous
#include <cuda_runtime.h>
#include <cuda_fp16.h>
#include <math.h>

typedef unsigned int u32;
typedef unsigned long long u64;

// Problem constants
constexpr int B_    = 8192;
constexpr int NE_   = 20000;
constexpr int H_    = 512;
constexpr int C_    = 50;
constexpr int KIN_  = 25600;          // C_*H_

// ---------------- scratch (static device memory; no allocations) -------------
__device__ float g_xs[(size_t)B_ * 3 * H_];
__device__ float g_part0[B_ * 6];
__device__ float g_s0[3], g_t0[3];
__device__ float g_part1[B_ * 100];
__device__ float g_s1[C_], g_t1[C_];
__device__ __half g_a16[(size_t)B_ * KIN_];    // A fp16 (420 MB)
__device__ __half g_w16[(size_t)H_ * KIN_];    // fc_w fp16
__device__ __half g_e16[(size_t)NE_ * H_];     // ent fp16
__device__ __half g_z16[(size_t)B_ * H_];      // z fp16
__device__ float g_fc[B_ * H_];
__device__ float g_part2[256 * 1024];
__device__ float g_s2[H_], g_t2[H_];

// ---------------- PTX helpers (portable: sm_80+ instructions only) -----------
static __device__ __forceinline__ u32 smem_u32(const void* p) {
    u32 a;
    asm("{ .reg .u64 t; cvta.to.shared.u64 t, %1; cvt.u32.u64 %0, t; }" : "=r"(a) : "l"(p));
    return a;
}

#define CP_ASYNC16(saddr, gptr, srcsz) \
    asm volatile("cp.async.cg.shared.global [%0], [%1], 16, %2;" \
                 :: "r"(saddr), "l"(gptr), "r"(srcsz) : "memory")
#define CP_COMMIT() asm volatile("cp.async.commit_group;" ::: "memory")

#define LDM_X4(r0, r1, r2, r3, addr) \
    asm volatile("ldmatrix.sync.aligned.m8n8.x4.shared.b16 {%0,%1,%2,%3}, [%4];" \
                 : "=r"(r0), "=r"(r1), "=r"(r2), "=r"(r3) : "r"(addr))

#define MMA16816(d, a, b0, b1) \
    asm volatile("mma.sync.aligned.m16n8k16.row.col.f32.f16.f16.f32 " \
                 "{%0,%1,%2,%3},{%4,%5,%6,%7},{%8,%9},{%0,%1,%2,%3};" \
                 : "+f"((d)[0]), "+f"((d)[1]), "+f"((d)[2]), "+f"((d)[3]) \
                 : "r"((a)[0]), "r"((a)[1]), "r"((a)[2]), "r"((a)[3]), \
                   "r"(b0), "r"(b1))

// ======================= K1: gather + bn0 partial stats ======================
__global__ void k_gather(const int* __restrict__ facts, const float* __restrict__ ent,
                         const float* __restrict__ rel, const float* __restrict__ erb)
{
    int b = blockIdx.x, t = threadIdx.x;
    int f0 = facts[b * 3 + 0];
    int f1 = facts[b * 3 + 1];
    const float* r0 = ent + (size_t)f0 * H_;
    const float* r1 = rel + (size_t)f1 * H_;
    const float* r2 = erb + (size_t)f0 * H_;
    float* xb = g_xs + (size_t)b * 3 * H_;

    float s[3] = {0.f, 0.f, 0.f}, q[3] = {0.f, 0.f, 0.f};
    for (int h = t; h < H_; h += 128) {
        float v0 = r0[h], v1 = r1[h], v2 = r2[h];
        xb[h] = v0; xb[H_ + h] = v1; xb[2 * H_ + h] = v2;
        s[0] += v0; q[0] += v0 * v0;
        s[1] += v1; q[1] += v1 * v1;
        s[2] += v2; q[2] += v2 * v2;
    }
    __shared__ float red[4][6];
    #pragma unroll
    for (int i = 0; i < 3; i++) {
        #pragma unroll
        for (int o = 16; o; o >>= 1) {
            s[i] += __shfl_xor_sync(0xffffffffu, s[i], o);
            q[i] += __shfl_xor_sync(0xffffffffu, q[i], o);
        }
    }
    int w = t >> 5, ln = t & 31;
    if (ln == 0) {
        #pragma unroll
        for (int i = 0; i < 3; i++) { red[w][i] = s[i]; red[w][3 + i] = q[i]; }
    }
    __syncthreads();
    if (t < 6) g_part0[b * 6 + t] = red[0][t] + red[1][t] + red[2][t] + red[3][t];
}

// ======================= K2: finalize bn0 =====================================
__global__ void k_fin0(const float* __restrict__ gg, const float* __restrict__ bb)
{
    __shared__ double sd[256];
    __shared__ double tot[6];
    int t = threadIdx.x;
    for (int st = 0; st < 6; st++) {
        double a = 0.0;
        for (int j = t; j < B_; j += 256) a += (double)g_part0[j * 6 + st];
        sd[t] = a; __syncthreads();
        for (int o = 128; o; o >>= 1) { if (t < o) sd[t] += sd[t + o]; __syncthreads(); }
        if (t == 0) tot[st] = sd[0];
        __syncthreads();
    }
    if (t < 3) {
        double cnt  = (double)B_ * (double)H_;
        double mean = tot[t] / cnt;
        double var  = tot[3 + t] / cnt - mean * mean;
        double sc   = (double)gg[t] / sqrt(var + 1e-5);
        g_s0[t] = (float)sc;
        g_t0[t] = (float)((double)bb[t] - mean * sc);
    }
}

// ======================= K3: conv + bn1 partial stats =========================
__global__ void k_conv_stats(const float* __restrict__ cw, const float* __restrict__ cb)
{
    __shared__ float xn[3][514];
    __shared__ float w[450];
    __shared__ float cbs[C_];
    __shared__ float ssum[C_], ssq[C_];
    int b = blockIdx.x, t = threadIdx.x;

    for (int i = t; i < 450; i += 256) w[i] = cw[i];
    if (t < C_) { cbs[t] = cb[t]; ssum[t] = 0.f; ssq[t] = 0.f; }
    for (int i = t; i < 3 * H_; i += 256) {
        int ch = i >> 9, h = i & 511;
        xn[ch][h + 1] = g_xs[((size_t)b * 3 + ch) * H_ + h] * g_s0[ch] + g_t0[ch];
    }
    if (t < 3) { xn[t][0] = 0.f; xn[t][513] = 0.f; }
    __syncthreads();

    for (int c = 0; c < C_; c++) {
        float w0 = w[c*9+0], w1 = w[c*9+1], w2 = w[c*9+2];
        float w3 = w[c*9+3], w4 = w[c*9+4], w5 = w[c*9+5];
        float w6 = w[c*9+6], w7 = w[c*9+7], w8 = w[c*9+8];
        float bs = 0.f, bq = 0.f;
        #pragma unroll
        for (int hh = 0; hh < 2; hh++) {
            int h = t + hh * 256;
            float y = cbs[c]
                + w0 * xn[0][h] + w1 * xn[0][h + 1] + w2 * xn[0][h + 2]
                + w3 * xn[1][h] + w4 * xn[1][h + 1] + w5 * xn[1][h + 2]
                + w6 * xn[2][h] + w7 * xn[2][h + 1] + w8 * xn[2][h + 2];
            bs += y; bq += y * y;
        }
        #pragma unroll
        for (int o = 16; o; o >>= 1) {
            bs += __shfl_xor_sync(0xffffffffu, bs, o);
            bq += __shfl_xor_sync(0xffffffffu, bq, o);
        }
        if ((t & 31) == 0) { atomicAdd(&ssum[c], bs); atomicAdd(&ssq[c], bq); }
    }
    __syncthreads();
    if (t < C_) {
        g_part1[(size_t)b * 100 + t]      = ssum[t];
        g_part1[(size_t)b * 100 + 50 + t] = ssq[t];
    }
}

// ======================= K4: finalize bn1 =====================================
__global__ void k_fin1(const float* __restrict__ gg, const float* __restrict__ bb)
{
    int c = blockIdx.x, t = threadIdx.x;
    __shared__ double sd[256];
    __shared__ double tS;
    double s = 0.0, q = 0.0;
    for (int j = t; j < B_; j += 256) {
        s += (double)g_part1[(size_t)j * 100 + c];
        q += (double)g_part1[(size_t)j * 100 + 50 + c];
    }
    sd[t] = s; __syncthreads();
    for (int o = 128; o; o >>= 1) { if (t < o) sd[t] += sd[t + o]; __syncthreads(); }
    if (t == 0) tS = sd[0];
    __syncthreads();
    sd[t] = q; __syncthreads();
    for (int o = 128; o; o >>= 1) { if (t < o) sd[t] += sd[t + o]; __syncthreads(); }
    if (t == 0) {
        double cnt  = (double)B_ * (double)H_;
        double mean = tS / cnt;
        double var  = sd[0] / cnt - mean * mean;
        double sc   = (double)gg[c] / sqrt(var + 1e-5);
        g_s1[c] = (float)sc;
        g_t1[c] = (float)((double)bb[c] - mean * sc);
    }
}

// ======================= K5: build A (fp16) ===================================
__global__ void k_build(const float* __restrict__ cw, const float* __restrict__ cb)
{
    __shared__ float xn[3][514];
    __shared__ float w[450];
    __shared__ float cbs[C_];
    __shared__ float s1s[C_], t1s[C_];
    int b = blockIdx.x, t = threadIdx.x;

    for (int i = t; i < 450; i += 256) w[i] = cw[i];
    if (t < C_) { cbs[t] = cb[t]; s1s[t] = g_s1[t]; t1s[t] = g_t1[t]; }
    for (int i = t; i < 3 * H_; i += 256) {
        int ch = i >> 9, h = i & 511;
        xn[ch][h + 1] = g_xs[((size_t)b * 3 + ch) * H_ + h] * g_s0[ch] + g_t0[ch];
    }
    if (t < 3) { xn[t][0] = 0.f; xn[t][513] = 0.f; }
    __syncthreads();

    __half* arow = g_a16 + (size_t)b * KIN_;
    for (int c = 0; c < C_; c++) {
        float w0 = w[c*9+0], w1 = w[c*9+1], w2 = w[c*9+2];
        float w3 = w[c*9+3], w4 = w[c*9+4], w5 = w[c*9+5];
        float w6 = w[c*9+6], w7 = w[c*9+7], w8 = w[c*9+8];
        float sc = s1s[c], tc = t1s[c], cbc = cbs[c];
        #pragma unroll
        for (int hh = 0; hh < 2; hh++) {
            int h = t + hh * 256;
            float y = cbc
                + w0 * xn[0][h] + w1 * xn[0][h + 1] + w2 * xn[0][h + 2]
                + w3 * xn[1][h] + w4 * xn[1][h + 1] + w5 * xn[1][h + 2]
                + w6 * xn[2][h] + w7 * xn[2][h + 1] + w8 * xn[2][h + 2];
            float r = fmaxf(fmaf(y, sc, tc), 0.f);
            arow[c * H_ + h] = __float2half_rn(r);
        }
    }
}

// ======================= split: fp32 -> fp16 ==================================
__global__ void k_cvt16(const float* __restrict__ src, __half* __restrict__ dst, long long n)
{
    long long i = (long long)blockIdx.x * 256 + threadIdx.x;
    if (i < n) dst[i] = __float2half_rn(src[i]);
}

// ======================= fp16 NT GEMM (mma.sync m16n8k16) ====================
// C[m,n] = sum_k A[m,k] * B[n,k].  A: MxK row-major fp16, B: NxK row-major fp16.
// Block 128x128, K-tile 64, 8 warps (2m x 4n) with 64x32 warp tiles.
// 3-stage cp.async pipeline, one __syncthreads per K-tile. Occupancy 2.
// GRID: x = n-tile (fastest), y = m-tile  => concurrent CTAs share A via L2.
// Requires M%128==0, K%64==0; N%8==0 (guarded).
constexpr int RB   = 144;                    // padded row bytes (64 fp16 + 8 pad)
constexpr int ASZ  = 128 * RB;               // 18432 B (A or B tile)
constexpr int STG  = 2 * ASZ;                // 36864 B per stage (A + B)
constexpr int NSTG = 3;
constexpr int GEMM_SMEM = NSTG * STG;        // 110592 B

__global__ __launch_bounds__(256, 2)
void k_gemm(const __half* __restrict__ A, const __half* __restrict__ Bm,
            float* __restrict__ Cm, int N, int Kd, const float* __restrict__ bias)
{
    extern __shared__ char smem[];
    const u32 sb = smem_u32(smem);
    const int tid  = threadIdx.x;
    const int w    = tid >> 5, lane = tid & 31;
    const int mBase = blockIdx.y * 128;      // m on y
    const int nBase = blockIdx.x * 128;      // n on x (fastest) -> A L2 reuse

    // per-thread cp.async geometry: 4 chunks (16B) each for A and B
    size_t gA[4]; u32 sA[4];
    size_t gB[4]; u32 sB[4]; u32 vB[4];
    #pragma unroll
    for (int i = 0; i < 4; i++) {
        int idx = tid + i * 256;              // 0..1023
        int r = idx >> 3, c = idx & 7;
        gA[i] = (size_t)(mBase + r) * Kd + c * 8;
        sA[i] = r * RB + c * 16;
        int n = nBase + r;
        int ok = (n < N);
        gB[i] = (size_t)(ok ? n : 0) * Kd + c * 8;
        sB[i] = r * RB + c * 16;
        vB[i] = ok ? 16u : 0u;
    }

    const int nT = Kd >> 6;

    // ldmatrix source addresses (per warp), relative to stage base
    const int wm = (w & 1) * 64;
    const int wn = (w >> 1) * 32;
    const u32 lrow = (lane & 15), lhalf = (lane >> 4) << 4;
    u32 aRel[4], bRel[2];
    #pragma unroll
    for (int i = 0; i < 4; i++) aRel[i] = (wm + i * 16 + lrow) * RB + lhalf;
    #pragma unroll
    for (int jj = 0; jj < 2; jj++) bRel[jj] = ASZ + (wn + jj * 16 + lrow) * RB + lhalf;

    float acc[4][4][4];
    #pragma unroll
    for (int i = 0; i < 4; i++)
        #pragma unroll
        for (int j = 0; j < 4; j++)
            #pragma unroll
            for (int q = 0; q < 4; q++) acc[i][j][q] = 0.f;

    // prologue: stages 0..NSTG-2
    #pragma unroll
    for (int p = 0; p < NSTG - 1; p++) {
        if (p < nT) {
            const u32 st = sb + p * STG;
            const size_t ko = (size_t)p * 64;
            #pragma unroll
            for (int i = 0; i < 4; i++) CP_ASYNC16(st + sA[i], A + gA[i] + ko, 16u);
            #pragma unroll
            for (int i = 0; i < 4; i++) CP_ASYNC16(st + ASZ + sB[i], Bm + gB[i] + ko, vB[i]);
        }
        CP_COMMIT();
    }

    for (int t = 0; t < nT; t++) {
        asm volatile("cp.async.wait_group 1;" ::: "memory");
        __syncthreads();

        // issue K-tile t+NSTG-1 into its stage (empty commit keeps ledger uniform)
        {
            int nt = t + NSTG - 1;
            if (nt < nT) {
                const u32 st = sb + (nt % NSTG) * STG;
                const size_t ko = (size_t)nt * 64;
                #pragma unroll
                for (int i = 0; i < 4; i++) CP_ASYNC16(st + sA[i], A + gA[i] + ko, 16u);
                #pragma unroll
                for (int i = 0; i < 4; i++) CP_ASYNC16(st + ASZ + sB[i], Bm + gB[i] + ko, vB[i]);
            }
            CP_COMMIT();
        }

        const u32 stoff = sb + (t % NSTG) * STG;
        #pragma unroll
        for (int s = 0; s < 4; s++) {
            u32 ar[4][4], br[2][4];
            #pragma unroll
            for (int i = 0; i < 4; i++)
                LDM_X4(ar[i][0], ar[i][1], ar[i][2], ar[i][3], stoff + aRel[i] + s * 32);
            #pragma unroll
            for (int jj = 0; jj < 2; jj++)
                LDM_X4(br[jj][0], br[jj][1], br[jj][2], br[jj][3], stoff + bRel[jj] + s * 32);
            #pragma unroll
            for (int i = 0; i < 4; i++) {
                #pragma unroll
                for (int j = 0; j < 4; j++) {
                    MMA16816(acc[i][j], ar[i], br[j >> 1][j & 1], br[j >> 1][(j & 1) + 2]);
                }
            }
        }
    }

    // epilogue
    const int mRow = mBase + wm + (lane >> 2);
    const int nCol = nBase + wn + ((lane & 3) << 1);
    #pragma unroll
    for (int i = 0; i < 4; i++) {
        #pragma unroll
        for (int j = 0; j < 4; j++) {
            int n = nCol + j * 8;
            if (n < N) {
                float bx = 0.f, by = 0.f;
                if (bias) { bx = bias[n]; by = bias[n + 1]; }
                int m0 = mRow + i * 16;
                float2 v0; v0.x = acc[i][j][0] + bx; v0.y = acc[i][j][1] + by;
                float2 v1; v1.x = acc[i][j][2] + bx; v1.y = acc[i][j][3] + by;
                *(float2*)(Cm + (size_t)m0 * N + n) = v0;
                *(float2*)(Cm + (size_t)(m0 + 8) * N + n) = v1;
            }
        }
    }
}

// ======================= K7: bn2 partial stats ================================
__global__ void k_stats2_part()
{
    int blk = blockIdx.x, t = threadIdx.x;
    float s0 = 0.f, q0 = 0.f, s1 = 0.f, q1 = 0.f;
    int r0 = blk * 32;
    for (int r = 0; r < 32; r++) {
        const float* row = g_fc + (size_t)(r0 + r) * H_;
        float a = row[t];
        float b = row[t + 256];
        s0 += a; q0 += a * a;
        s1 += b; q1 += b * b;
    }
    g_part2[blk * 1024 + t]       = s0;
    g_part2[blk * 1024 + 256 + t] = q0;
    g_part2[blk * 1024 + 512 + t] = s1;
    g_part2[blk * 1024 + 768 + t] = q1;
}

// ======================= K8: finalize bn2 =====================================
__global__ void k_fin2(const float* __restrict__ gg, const float* __restrict__ bb)
{
    int n = blockIdx.x * 256 + threadIdx.x;
    int so = (n < 256) ? n : (256 + n);
    int qo = so + 256;
    double s = 0.0, q = 0.0;
    for (int j = 0; j < 256; j++) {
        s += (double)g_part2[j * 1024 + so];
        q += (double)g_part2[j * 1024 + qo];
    }
    double mean = s / (double)B_;
    double var  = q / (double)B_ - mean * mean;
    double sc   = (double)gg[n] / sqrt(var + 1e-5);
    g_s2[n] = (float)sc;
    g_t2[n] = (float)((double)bb[n] - mean * sc);
}

// ======================= K9: bn2+relu -> z fp16 ===============================
__global__ void k_bn2relu()
{
    int idx = blockIdx.x * 256 + threadIdx.x;     // over B_*H_
    int c = idx & 511;
    float v = fmaxf(fmaf(g_fc[idx], g_s2[c], g_t2[c]), 0.f);
    g_z16[idx] = __float2half_rn(v);
}

// ======================= K11: row log_softmax (online, 2 passes) ==============
__global__ void k_lsm(float* __restrict__ out)
{
    int b = blockIdx.x, t = threadIdx.x;
    float* p = out + (size_t)b * NE_;
    __shared__ float rm[8], rs[8];
    __shared__ float lseS;

    float m = -3.0e38f, s = 0.f;
    for (int i = t; i < NE_; i += 256) {
        float v = p[i];
        if (v > m) { s = s * __expf(m - v) + 1.f; m = v; }
        else       { s += __expf(v - m); }
    }
    #pragma unroll
    for (int o = 16; o; o >>= 1) {
        float mo = __shfl_xor_sync(0xffffffffu, m, o);
        float so = __shfl_xor_sync(0xffffffffu, s, o);
        float M = fmaxf(m, mo);
        s = s * __expf(m - M) + so * __expf(mo - M);
        m = M;
    }
    if ((t & 31) == 0) { rm[t >> 5] = m; rs[t >> 5] = s; }
    __syncthreads();
    if (t == 0) {
        float M = rm[0], S = rs[0];
        for (int j = 1; j < 8; j++) {
            float M2 = fmaxf(M, rm[j]);
            S = S * __expf(M - M2) + rs[j] * __expf(rm[j] - M2);
            M = M2;
        }
        lseS = M + logf(S);
    }
    __syncthreads();
    float lse = lseS;
    for (int i = t; i < NE_; i += 256) p[i] -= lse;
}

// ======================= launch ===============================================
extern "C" void kernel_launch(void* const* d_in, const int* in_sizes, int n_in,
                              void* d_out, int out_size)
{
    const int*   facts = (const int*)  d_in[0];
    const float* ent   = (const float*)d_in[1];
    const float* rel   = (const float*)d_in[2];
    const float* erb   = (const float*)d_in[3];
    const float* cw    = (const float*)d_in[4];
    const float* cb    = (const float*)d_in[5];
    const float* fcw   = (const float*)d_in[6];
    const float* fcb   = (const float*)d_in[7];
    const float* b0g   = (const float*)d_in[8];
    const float* b0b   = (const float*)d_in[9];
    const float* b1g   = (const float*)d_in[10];
    const float* b1b   = (const float*)d_in[11];
    const float* b2g   = (const float*)d_in[12];
    const float* b2b   = (const float*)d_in[13];
    float* out = (float*)d_out;

    cudaFuncSetAttribute(k_gemm, cudaFuncAttributeMaxDynamicSharedMemorySize, GEMM_SMEM);

    __half *p_a16, *p_w16, *p_e16, *p_z16;
    float *p_fc;
    cudaGetSymbolAddress((void**)&p_a16, g_a16);
    cudaGetSymbolAddress((void**)&p_w16, g_w16);
    cudaGetSymbolAddress((void**)&p_e16, g_e16);
    cudaGetSymbolAddress((void**)&p_z16, g_z16);
    cudaGetSymbolAddress((void**)&p_fc,  g_fc);

    k_gather<<<B_, 128>>>(facts, ent, rel, erb);
    k_fin0<<<1, 256>>>(b0g, b0b);
    k_conv_stats<<<B_, 256>>>(cw, cb);
    k_fin1<<<C_, 256>>>(b1g, b1b);
    k_build<<<B_, 256>>>(cw, cb);

    {
        long long nW = (long long)H_ * KIN_;
        k_cvt16<<<(u32)((nW + 255) / 256), 256>>>(fcw, p_w16, nW);
        long long nE = (long long)NE_ * H_;
        k_cvt16<<<(u32)((nE + 255) / 256), 256>>>(ent, p_e16, nE);
    }

    // FC: (8192, 25600) x (512, 25600)^T -> (8192, 512), + bias
    // grid: x = n-tiles (4), y = m-tiles (64)  => A shared via L2 within wave
    k_gemm<<<dim3(H_ / 128, B_ / 128), 256, GEMM_SMEM>>>(
        p_a16, p_w16, p_fc, H_, KIN_, fcb);

    k_stats2_part<<<256, 256>>>();
    k_fin2<<<2, 256>>>(b2g, b2b);
    k_bn2relu<<<(B_ * H_) / 256, 256>>>();

    // score: (8192, 512) x (20000, 512)^T -> (8192, 20000)
    // grid: x = n-tiles (157), y = m-tiles (64) => z tile + E L2-resident
    k_gemm<<<dim3((NE_ + 127) / 128, B_ / 128), 256, GEMM_SMEM>>>(
        p_z16, p_e16, out, NE_, H_, nullptr);

    k_lsm<<<B_, 256>>>(out);
}

// round 10
// speedup vs baseline: 1.8790x; 1.2226x over previous
#include <cuda_runtime.h>
#include <cuda_fp16.h>
#include <math.h>

typedef unsigned int u32;
typedef unsigned long long u64;

// Problem constants
constexpr int B_    = 8192;
constexpr int NE_   = 20000;
constexpr int H_    = 512;
constexpr int C_    = 50;
constexpr int KIN_  = 25600;          // C_*H_

// ---------------- scratch (static device memory; no allocations) -------------
__device__ float g_xs[(size_t)B_ * 3 * H_];
__device__ float g_part0[B_ * 6];
__device__ float g_s0[3], g_t0[3];
__device__ float g_part1[(size_t)B_ * 54];     // per-block V(9) + M(45)
__device__ double g_v54[54];
__device__ float g_s1[C_], g_t1[C_];
__device__ __half g_a16[(size_t)B_ * KIN_];    // A fp16 (420 MB)
__device__ __half g_w16[(size_t)H_ * KIN_];    // fc_w fp16
__device__ __half g_e16[(size_t)NE_ * H_];     // ent fp16
__device__ __half g_z16[(size_t)B_ * H_];      // z fp16
__device__ float g_fc[B_ * H_];
__device__ float g_part2[256 * 1024];
__device__ float g_s2[H_], g_t2[H_];

// ---------------- PTX helpers (portable: sm_80+ instructions only) -----------
static __device__ __forceinline__ u32 smem_u32(const void* p) {
    u32 a;
    asm("{ .reg .u64 t; cvta.to.shared.u64 t, %1; cvt.u32.u64 %0, t; }" : "=r"(a) : "l"(p));
    return a;
}

#define CP_ASYNC16(saddr, gptr, srcsz) \
    asm volatile("cp.async.cg.shared.global [%0], [%1], 16, %2;" \
                 :: "r"(saddr), "l"(gptr), "r"(srcsz) : "memory")
#define CP_COMMIT() asm volatile("cp.async.commit_group;" ::: "memory")

#define LDM_X4(r0, r1, r2, r3, addr) \
    asm volatile("ldmatrix.sync.aligned.m8n8.x4.shared.b16 {%0,%1,%2,%3}, [%4];" \
                 : "=r"(r0), "=r"(r1), "=r"(r2), "=r"(r3) : "r"(addr))

#define MMA16816(d, a, b0, b1) \
    asm volatile("mma.sync.aligned.m16n8k16.row.col.f32.f16.f16.f32 " \
                 "{%0,%1,%2,%3},{%4,%5,%6,%7},{%8,%9},{%0,%1,%2,%3};" \
                 : "+f"((d)[0]), "+f"((d)[1]), "+f"((d)[2]), "+f"((d)[3]) \
                 : "r"((a)[0]), "r"((a)[1]), "r"((a)[2]), "r"((a)[3]), \
                   "r"(b0), "r"(b1))

// ======================= K1: gather + bn0 partial stats ======================
__global__ void k_gather(const int* __restrict__ facts, const float* __restrict__ ent,
                         const float* __restrict__ rel, const float* __restrict__ erb)
{
    int b = blockIdx.x, t = threadIdx.x;
    int f0 = facts[b * 3 + 0];
    int f1 = facts[b * 3 + 1];
    const float* r0 = ent + (size_t)f0 * H_;
    const float* r1 = rel + (size_t)f1 * H_;
    const float* r2 = erb + (size_t)f0 * H_;
    float* xb = g_xs + (size_t)b * 3 * H_;

    float s[3] = {0.f, 0.f, 0.f}, q[3] = {0.f, 0.f, 0.f};
    for (int h = t; h < H_; h += 128) {
        float v0 = r0[h], v1 = r1[h], v2 = r2[h];
        xb[h] = v0; xb[H_ + h] = v1; xb[2 * H_ + h] = v2;
        s[0] += v0; q[0] += v0 * v0;
        s[1] += v1; q[1] += v1 * v1;
        s[2] += v2; q[2] += v2 * v2;
    }
    __shared__ float red[4][6];
    #pragma unroll
    for (int i = 0; i < 3; i++) {
        #pragma unroll
        for (int o = 16; o; o >>= 1) {
            s[i] += __shfl_xor_sync(0xffffffffu, s[i], o);
            q[i] += __shfl_xor_sync(0xffffffffu, q[i], o);
        }
    }
    int w = t >> 5, ln = t & 31;
    if (ln == 0) {
        #pragma unroll
        for (int i = 0; i < 3; i++) { red[w][i] = s[i]; red[w][3 + i] = q[i]; }
    }
    __syncthreads();
    if (t < 6) g_part0[b * 6 + t] = red[0][t] + red[1][t] + red[2][t] + red[3][t];
}

// ======================= K2: finalize bn0 (grid=3, one block per channel) =====
__global__ void k_fin0(const float* __restrict__ gg, const float* __restrict__ bb)
{
    int c = blockIdx.x, t = threadIdx.x;
    __shared__ double sd[256], sq[256];
    double s = 0.0, q = 0.0;
    for (int j = t; j < B_; j += 256) {
        s += (double)g_part0[j * 6 + c];
        q += (double)g_part0[j * 6 + 3 + c];
    }
    sd[t] = s; sq[t] = q; __syncthreads();
    for (int o = 128; o; o >>= 1) {
        if (t < o) { sd[t] += sd[t + o]; sq[t] += sq[t + o]; }
        __syncthreads();
    }
    if (t == 0) {
        double cnt  = (double)B_ * (double)H_;
        double mean = sd[0] / cnt;
        double var  = sq[0] / cnt - mean * mean;
        double sc   = (double)gg[c] / sqrt(var + 1e-5);
        g_s0[c] = (float)sc;
        g_t0[c] = (float)((double)bb[c] - mean * sc);
    }
}

// ======================= K3: conv stats via moment matrix ======================
// Per block: V[9] = sum_h v(h), M[45] = upper-tri of sum_h v v^T, where
// v(h) = (xn0[h..h+2], xn1[h..h+2], xn2[h..h+2]).  Channel stats derive later.
__global__ void k_conv_stats()
{
    __shared__ float xn[3][514];
    __shared__ float red[8][54];
    int b = blockIdx.x, t = threadIdx.x;

    for (int i = t; i < 3 * H_; i += 256) {
        int ch = i >> 9, h = i & 511;
        xn[ch][h + 1] = g_xs[((size_t)b * 3 + ch) * H_ + h] * g_s0[ch] + g_t0[ch];
    }
    if (t < 3) { xn[t][0] = 0.f; xn[t][513] = 0.f; }
    __syncthreads();

    float acc[54];
    #pragma unroll
    for (int i = 0; i < 54; i++) acc[i] = 0.f;

    #pragma unroll
    for (int hh = 0; hh < 2; hh++) {
        int h = t + hh * 256;
        float v[9];
        #pragma unroll
        for (int i = 0; i < 3; i++)
            #pragma unroll
            for (int k = 0; k < 3; k++)
                v[i * 3 + k] = xn[i][h + k];
        #pragma unroll
        for (int i = 0; i < 9; i++) acc[i] += v[i];
        int idx = 9;
        #pragma unroll
        for (int i = 0; i < 9; i++)
            #pragma unroll
            for (int j = 0; j <= i; j++)
                acc[idx++] += v[i] * v[j];
    }

    // warp reduce 54 values
    #pragma unroll
    for (int i = 0; i < 54; i++) {
        #pragma unroll
        for (int o = 16; o; o >>= 1)
            acc[i] += __shfl_xor_sync(0xffffffffu, acc[i], o);
    }
    int w = t >> 5, ln = t & 31;
    if (ln == 0) {
        #pragma unroll
        for (int i = 0; i < 54; i++) red[w][i] = acc[i];
    }
    __syncthreads();
    if (t < 54) {
        float a = 0.f;
        #pragma unroll
        for (int j = 0; j < 8; j++) a += red[j][t];
        g_part1[(size_t)b * 54 + t] = a;
    }
}

// ======================= K4a: reduce moments over blocks (grid=54) ============
__global__ void k_fin1a()
{
    int comp = blockIdx.x, t = threadIdx.x;
    __shared__ double sd[256];
    double s = 0.0;
    for (int j = t; j < B_; j += 256) s += (double)g_part1[(size_t)j * 54 + comp];
    sd[t] = s; __syncthreads();
    for (int o = 128; o; o >>= 1) { if (t < o) sd[t] += sd[t + o]; __syncthreads(); }
    if (t == 0) g_v54[comp] = sd[0];
}

// ======================= K4b: per-channel bn1 params via quadratic form =======
__global__ void k_fin1b(const float* __restrict__ cw, const float* __restrict__ cb,
                        const float* __restrict__ gg, const float* __restrict__ bb)
{
    int c = threadIdx.x;
    if (c < C_) {
        double w[9];
        #pragma unroll
        for (int i = 0; i < 9; i++) w[i] = (double)cw[c * 9 + i];
        double cbv = (double)cb[c];
        double N = (double)B_ * (double)H_;
        double dot = 0.0;
        #pragma unroll
        for (int i = 0; i < 9; i++) dot += w[i] * g_v54[i];
        double sy = cbv * N + dot;
        double sq = cbv * cbv * N + 2.0 * cbv * dot;
        #pragma unroll
        for (int i = 0; i < 9; i++)
            #pragma unroll
            for (int j = 0; j <= i; j++) {
                double m = g_v54[9 + i * (i + 1) / 2 + j];
                sq += ((i == j) ? 1.0 : 2.0) * w[i] * w[j] * m;
            }
        double mean = sy / N;
        double var  = sq / N - mean * mean;
        double sc   = (double)gg[c] / sqrt(var + 1e-5);
        g_s1[c] = (float)sc;
        g_t1[c] = (float)((double)bb[c] - mean * sc);
    }
}

// ======================= K5: build A (fp16), register-hoisted =================
__global__ void k_build(const float* __restrict__ cw, const float* __restrict__ cb)
{
    __shared__ float xn[3][514];
    __shared__ float4 w4[150];        // 50 ch x 3 float4 (9 weights + 3 pad)
    __shared__ float2 p2[C_];         // (a1, b1): r = relu(y*a1 + b1)
    int b = blockIdx.x, t = threadIdx.x;

    for (int i = t; i < 600; i += 256) {
        int c = i / 12, j = i % 12;
        ((float*)w4)[i] = (j < 9) ? cw[c * 9 + j] : 0.f;
    }
    if (t < C_) {
        float s1 = g_s1[t], t1 = g_t1[t];
        p2[t] = make_float2(s1, cb[t] * s1 + t1);
    }
    for (int i = t; i < 3 * H_; i += 256) {
        int ch = i >> 9, h = i & 511;
        xn[ch][h + 1] = g_xs[((size_t)b * 3 + ch) * H_ + h] * g_s0[ch] + g_t0[ch];
    }
    if (t < 3) { xn[t][0] = 0.f; xn[t][513] = 0.f; }
    __syncthreads();

    float v[2][9];
    #pragma unroll
    for (int hh = 0; hh < 2; hh++) {
        int h = t + hh * 256;
        #pragma unroll
        for (int i = 0; i < 3; i++)
            #pragma unroll
            for (int k = 0; k < 3; k++)
                v[hh][i * 3 + k] = xn[i][h + k];
    }

    __half* arow = g_a16 + (size_t)b * KIN_;
    for (int c = 0; c < C_; c++) {
        float4 wa = w4[c * 3 + 0];
        float4 wb = w4[c * 3 + 1];
        float4 wc = w4[c * 3 + 2];
        float2 ab = p2[c];
        #pragma unroll
        for (int hh = 0; hh < 2; hh++) {
            float y = wa.x * v[hh][0] + wa.y * v[hh][1] + wa.z * v[hh][2]
                    + wa.w * v[hh][3] + wb.x * v[hh][4] + wb.y * v[hh][5]
                    + wb.z * v[hh][6] + wb.w * v[hh][7] + wc.x * v[hh][8];
            float r = fmaxf(fmaf(y, ab.x, ab.y), 0.f);
            arow[c * H_ + t + hh * 256] = __float2half_rn(r);
        }
    }
}

// ======================= split: fp32 -> fp16 ==================================
__global__ void k_cvt16(const float* __restrict__ src, __half* __restrict__ dst, long long n)
{
    long long i = (long long)blockIdx.x * 256 + threadIdx.x;
    if (i < n) dst[i] = __float2half_rn(src[i]);
}

// ======================= fp16 NT GEMM (mma.sync m16n8k16) ====================
// Block 128x128, K-tile 64, 8 warps (2m x 4n) with 64x32 warp tiles.
// 3-stage cp.async pipeline, one __syncthreads per K-tile. Occupancy 2.
// GRID: x = n-tile (fastest), y = m-tile.
constexpr int RB   = 144;                    // padded row bytes (64 fp16 + 8 pad)
constexpr int ASZ  = 128 * RB;               // 18432 B (A or B tile)
constexpr int STG  = 2 * ASZ;                // 36864 B per stage (A + B)
constexpr int NSTG = 3;
constexpr int GEMM_SMEM = NSTG * STG;        // 110592 B

__global__ __launch_bounds__(256, 2)
void k_gemm(const __half* __restrict__ A, const __half* __restrict__ Bm,
            float* __restrict__ Cm, int N, int Kd, const float* __restrict__ bias)
{
    extern __shared__ char smem[];
    const u32 sb = smem_u32(smem);
    const int tid  = threadIdx.x;
    const int w    = tid >> 5, lane = tid & 31;
    const int mBase = blockIdx.y * 128;
    const int nBase = blockIdx.x * 128;

    size_t gA[4]; u32 sA[4];
    size_t gB[4]; u32 sB[4]; u32 vB[4];
    #pragma unroll
    for (int i = 0; i < 4; i++) {
        int idx = tid + i * 256;
        int r = idx >> 3, c = idx & 7;
        gA[i] = (size_t)(mBase + r) * Kd + c * 8;
        sA[i] = r * RB + c * 16;
        int n = nBase + r;
        int ok = (n < N);
        gB[i] = (size_t)(ok ? n : 0) * Kd + c * 8;
        sB[i] = r * RB + c * 16;
        vB[i] = ok ? 16u : 0u;
    }

    const int nT = Kd >> 6;

    const int wm = (w & 1) * 64;
    const int wn = (w >> 1) * 32;
    const u32 lrow = (lane & 15), lhalf = (lane >> 4) << 4;
    u32 aRel[4], bRel[2];
    #pragma unroll
    for (int i = 0; i < 4; i++) aRel[i] = (wm + i * 16 + lrow) * RB + lhalf;
    #pragma unroll
    for (int jj = 0; jj < 2; jj++) bRel[jj] = ASZ + (wn + jj * 16 + lrow) * RB + lhalf;

    float acc[4][4][4];
    #pragma unroll
    for (int i = 0; i < 4; i++)
        #pragma unroll
        for (int j = 0; j < 4; j++)
            #pragma unroll
            for (int q = 0; q < 4; q++) acc[i][j][q] = 0.f;

    #pragma unroll
    for (int p = 0; p < NSTG - 1; p++) {
        if (p < nT) {
            const u32 st = sb + p * STG;
            const size_t ko = (size_t)p * 64;
            #pragma unroll
            for (int i = 0; i < 4; i++) CP_ASYNC16(st + sA[i], A + gA[i] + ko, 16u);
            #pragma unroll
            for (int i = 0; i < 4; i++) CP_ASYNC16(st + ASZ + sB[i], Bm + gB[i] + ko, vB[i]);
        }
        CP_COMMIT();
    }

    for (int t = 0; t < nT; t++) {
        asm volatile("cp.async.wait_group 1;" ::: "memory");
        __syncthreads();

        {
            int nt = t + NSTG - 1;
            if (nt < nT) {
                const u32 st = sb + (nt % NSTG) * STG;
                const size_t ko = (size_t)nt * 64;
                #pragma unroll
                for (int i = 0; i < 4; i++) CP_ASYNC16(st + sA[i], A + gA[i] + ko, 16u);
                #pragma unroll
                for (int i = 0; i < 4; i++) CP_ASYNC16(st + ASZ + sB[i], Bm + gB[i] + ko, vB[i]);
            }
            CP_COMMIT();
        }

        const u32 stoff = sb + (t % NSTG) * STG;
        #pragma unroll
        for (int s = 0; s < 4; s++) {
            u32 ar[4][4], br[2][4];
            #pragma unroll
            for (int i = 0; i < 4; i++)
                LDM_X4(ar[i][0], ar[i][1], ar[i][2], ar[i][3], stoff + aRel[i] + s * 32);
            #pragma unroll
            for (int jj = 0; jj < 2; jj++)
                LDM_X4(br[jj][0], br[jj][1], br[jj][2], br[jj][3], stoff + bRel[jj] + s * 32);
            #pragma unroll
            for (int i = 0; i < 4; i++) {
                #pragma unroll
                for (int j = 0; j < 4; j++) {
                    MMA16816(acc[i][j], ar[i], br[j >> 1][j & 1], br[j >> 1][(j & 1) + 2]);
                }
            }
        }
    }

    const int mRow = mBase + wm + (lane >> 2);
    const int nCol = nBase + wn + ((lane & 3) << 1);
    #pragma unroll
    for (int i = 0; i < 4; i++) {
        #pragma unroll
        for (int j = 0; j < 4; j++) {
            int n = nCol + j * 8;
            if (n < N) {
                float bx = 0.f, by = 0.f;
                if (bias) { bx = bias[n]; by = bias[n + 1]; }
                int m0 = mRow + i * 16;
                float2 v0; v0.x = acc[i][j][0] + bx; v0.y = acc[i][j][1] + by;
                float2 v1; v1.x = acc[i][j][2] + bx; v1.y = acc[i][j][3] + by;
                *(float2*)(Cm + (size_t)m0 * N + n) = v0;
                *(float2*)(Cm + (size_t)(m0 + 8) * N + n) = v1;
            }
        }
    }
}

// ======================= K7: bn2 partial stats ================================
__global__ void k_stats2_part()
{
    int blk = blockIdx.x, t = threadIdx.x;
    float s0 = 0.f, q0 = 0.f, s1 = 0.f, q1 = 0.f;
    int r0 = blk * 32;
    for (int r = 0; r < 32; r++) {
        const float* row = g_fc + (size_t)(r0 + r) * H_;
        float a = row[t];
        float b = row[t + 256];
        s0 += a; q0 += a * a;
        s1 += b; q1 += b * b;
    }
    g_part2[blk * 1024 + t]       = s0;
    g_part2[blk * 1024 + 256 + t] = q0;
    g_part2[blk * 1024 + 512 + t] = s1;
    g_part2[blk * 1024 + 768 + t] = q1;
}

// ======================= K8: finalize bn2 =====================================
__global__ void k_fin2(const float* __restrict__ gg, const float* __restrict__ bb)
{
    int n = blockIdx.x * 256 + threadIdx.x;
    int so = (n < 256) ? n : (256 + n);
    int qo = so + 256;
    double s = 0.0, q = 0.0;
    for (int j = 0; j < 256; j++) {
        s += (double)g_part2[j * 1024 + so];
        q += (double)g_part2[j * 1024 + qo];
    }
    double mean = s / (double)B_;
    double var  = q / (double)B_ - mean * mean;
    double sc   = (double)gg[n] / sqrt(var + 1e-5);
    g_s2[n] = (float)sc;
    g_t2[n] = (float)((double)bb[n] - mean * sc);
}

// ======================= K9: bn2+relu -> z fp16 ===============================
__global__ void k_bn2relu()
{
    int idx = blockIdx.x * 256 + threadIdx.x;
    int c = idx & 511;
    float v = fmaxf(fmaf(g_fc[idx], g_s2[c], g_t2[c]), 0.f);
    g_z16[idx] = __float2half_rn(v);
}

// ======================= K11: row log_softmax (online, 2 passes) ==============
__global__ void k_lsm(float* __restrict__ out)
{
    int b = blockIdx.x, t = threadIdx.x;
    float* p = out + (size_t)b * NE_;
    __shared__ float rm[8], rs[8];
    __shared__ float lseS;

    float m = -3.0e38f, s = 0.f;
    for (int i = t; i < NE_; i += 256) {
        float v = p[i];
        if (v > m) { s = s * __expf(m - v) + 1.f; m = v; }
        else       { s += __expf(v - m); }
    }
    #pragma unroll
    for (int o = 16; o; o >>= 1) {
        float mo = __shfl_xor_sync(0xffffffffu, m, o);
        float so = __shfl_xor_sync(0xffffffffu, s, o);
        float M = fmaxf(m, mo);
        s = s * __expf(m - M) + so * __expf(mo - M);
        m = M;
    }
    if ((t & 31) == 0) { rm[t >> 5] = m; rs[t >> 5] = s; }
    __syncthreads();
    if (t == 0) {
        float M = rm[0], S = rs[0];
        for (int j = 1; j < 8; j++) {
            float M2 = fmaxf(M, rm[j]);
            S = S * __expf(M - M2) + rs[j] * __expf(rm[j] - M2);
            M = M2;
        }
        lseS = M + logf(S);
    }
    __syncthreads();
    float lse = lseS;
    for (int i = t; i < NE_; i += 256) p[i] -= lse;
}

// ======================= launch ===============================================
extern "C" void kernel_launch(void* const* d_in, const int* in_sizes, int n_in,
                              void* d_out, int out_size)
{
    const int*   facts = (const int*)  d_in[0];
    const float* ent   = (const float*)d_in[1];
    const float* rel   = (const float*)d_in[2];
    const float* erb   = (const float*)d_in[3];
    const float* cw    = (const float*)d_in[4];
    const float* cb    = (const float*)d_in[5];
    const float* fcw   = (const float*)d_in[6];
    const float* fcb   = (const float*)d_in[7];
    const float* b0g   = (const float*)d_in[8];
    const float* b0b   = (const float*)d_in[9];
    const float* b1g   = (const float*)d_in[10];
    const float* b1b   = (const float*)d_in[11];
    const float* b2g   = (const float*)d_in[12];
    const float* b2b   = (const float*)d_in[13];
    float* out = (float*)d_out;

    cudaFuncSetAttribute(k_gemm, cudaFuncAttributeMaxDynamicSharedMemorySize, GEMM_SMEM);

    __half *p_a16, *p_w16, *p_e16, *p_z16;
    float *p_fc;
    cudaGetSymbolAddress((void**)&p_a16, g_a16);
    cudaGetSymbolAddress((void**)&p_w16, g_w16);
    cudaGetSymbolAddress((void**)&p_e16, g_e16);
    cudaGetSymbolAddress((void**)&p_z16, g_z16);
    cudaGetSymbolAddress((void**)&p_fc,  g_fc);

    k_gather<<<B_, 128>>>(facts, ent, rel, erb);
    k_fin0<<<3, 256>>>(b0g, b0b);
    k_conv_stats<<<B_, 256>>>();
    k_fin1a<<<54, 256>>>();
    k_fin1b<<<1, 64>>>(cw, cb, b1g, b1b);
    k_build<<<B_, 256>>>(cw, cb);

    {
        long long nW = (long long)H_ * KIN_;
        k_cvt16<<<(u32)((nW + 255) / 256), 256>>>(fcw, p_w16, nW);
        long long nE = (long long)NE_ * H_;
        k_cvt16<<<(u32)((nE + 255) / 256), 256>>>(ent, p_e16, nE);
    }

    // FC: (8192, 25600) x (512, 25600)^T -> (8192, 512), + bias
    k_gemm<<<dim3(H_ / 128, B_ / 128), 256, GEMM_SMEM>>>(
        p_a16, p_w16, p_fc, H_, KIN_, fcb);

    k_stats2_part<<<256, 256>>>();
    k_fin2<<<2, 256>>>(b2g, b2b);
    k_bn2relu<<<(B_ * H_) / 256, 256>>>();

    // score: (8192, 512) x (20000, 512)^T -> (8192, 20000)
    k_gemm<<<dim3((NE_ + 127) / 128, B_ / 128), 256, GEMM_SMEM>>>(
        p_z16, p_e16, out, NE_, H_, nullptr);

    k_lsm<<<B_, 256>>>(out);
}